// round 17
// baseline (speedup 1.0000x reference)
#include <cuda_runtime.h>
#include <cuda_bf16.h>

#define BATCH   2048
#define N0      49
#define CH      768
#define MID     48
#define K1      36
#define K2      24
#define THREADS 320
#define WARPS   10

// Preprocessed weights (device globals).
//   g_w1t[r][j*CH + c] = bf16( se{r}_w1[c, j] )
//   g_w2p[r][((j/4)*CH + c)*4 + (j%4)] = bf16(w2[j,c])
//   g_clswt[o*CH + c]  = cls_w[c, o]  fp32
__device__ __nv_bfloat16 g_w1t[2][MID * CH];
__device__ __nv_bfloat16 g_w2p[2][MID * CH];
__device__ float         g_clswt[5 * CH];

__global__ void convert_weights_kernel(const float* __restrict__ w1a,
                                       const float* __restrict__ w2a,
                                       const float* __restrict__ w1b,
                                       const float* __restrict__ w2b,
                                       const float* __restrict__ clsw) {
    int i = blockIdx.x * blockDim.x + threadIdx.x;
    if (i < MID * CH) {
        int j = i / CH;
        int c = i - j * CH;
        g_w1t[0][i] = __float2bfloat16(w1a[c * MID + j]);
        g_w1t[1][i] = __float2bfloat16(w1b[c * MID + j]);
        int pidx = ((j >> 2) * CH + c) * 4 + (j & 3);
        g_w2p[0][pidx] = __float2bfloat16(w2a[i]);
        g_w2p[1][pidx] = __float2bfloat16(w2b[i]);
    }
    if (i < 5 * CH) {
        int o = i / CH;
        int c = i - o * CH;
        g_clswt[i] = clsw[c * 5 + o];
    }
}

// Shared memory (floats): sbuf[CH], csum[CH], gat[CH], hbuf[MID],
// ts[64], list[40] int, uns[16] int, uns2[16] int, red[80]
#define SM_FLOATS (CH + CH + CH + MID + 64 + 40 + 16 + 16 + 80)
#define SM_BYTES  (SM_FLOATS * 4)

// W1 GEMV partial: row j of W1t read as uint2 (4 bf16), sbuf as float4
__device__ __forceinline__ float w1_dot(const __nv_bfloat16* __restrict__ w1row,
                                        const float4* __restrict__ s4, int lane) {
    const uint2* wr = (const uint2*)w1row;
    float acc = 0.f;
    #pragma unroll
    for (int k = 0; k < 6; k++) {
        int p = lane + 32 * k;
        uint2 u = wr[p];
        __nv_bfloat162 h0 = *reinterpret_cast<__nv_bfloat162*>(&u.x);
        __nv_bfloat162 h1 = *reinterpret_cast<__nv_bfloat162*>(&u.y);
        float4 s = s4[p];
        acc += s.x * __low2float(h0) + s.y * __high2float(h0)
             + s.z * __low2float(h1) + s.w * __high2float(h1);
    }
    return acc;
}

// gates GEMV for one channel c: packed W2, 12 x LDG.64
__device__ __forceinline__ float w2_dot(const uint2* __restrict__ W2p,
                                        const float* __restrict__ hbuf, int c) {
    float acc = 0.f;
    #pragma unroll
    for (int j4 = 0; j4 < MID / 4; j4++) {
        uint2 u = W2p[j4 * CH + c];
        __nv_bfloat162 p0 = *reinterpret_cast<__nv_bfloat162*>(&u.x);
        __nv_bfloat162 p1 = *reinterpret_cast<__nv_bfloat162*>(&u.y);
        acc += hbuf[4 * j4]     * __low2float(p0)
             + hbuf[4 * j4 + 1] * __high2float(p0)
             + hbuf[4 * j4 + 2] * __low2float(p1)
             + hbuf[4 * j4 + 3] * __high2float(p1);
    }
    return acc;
}

__global__ __launch_bounds__(THREADS, 4)
void coatgft_kernel(const float* __restrict__ x,
                    const float* __restrict__ b1a, const float* __restrict__ b2a,
                    const float* __restrict__ b1b, const float* __restrict__ b2b,
                    const float* __restrict__ ln_g, const float* __restrict__ ln_b,
                    const float* __restrict__ cls_b,
                    float* __restrict__ out) {
    extern __shared__ float sm[];
    float* sbuf = sm;                    // [CH]
    float* csum = sbuf + CH;             // [CH]
    float* gat  = csum + CH;             // [CH]
    float* hbuf = gat + CH;              // [MID]
    float* ts   = hbuf + MID;            // [64]
    int*   list = (int*)(ts + 64);       // [40]
    int*   uns  = list + 40;             // [16]
    int*   uns2 = uns + 16;              // [16]
    float* red  = (float*)(uns2 + 16);   // [80]

    const int tid  = threadIdx.x;
    const int lane = tid & 31;
    const int warp = tid >> 5;
    const int b    = blockIdx.x;
    const float* __restrict__ xb = x + (size_t)b * N0 * CH;

    // ---- colmean + colsum over 49 rows, float4 (threads 0..191) ----
    if (tid < 192) {
        float4 a = make_float4(0.f, 0.f, 0.f, 0.f);
        #pragma unroll 7
        for (int r = 0; r < N0; r++) {
            float4 v = __ldcg((const float4*)(xb + (size_t)r * CH) + tid);
            a.x += v.x; a.y += v.y; a.z += v.z; a.w += v.w;
        }
        ((float4*)csum)[tid] = a;
        float4 m = make_float4(a.x * (1.0f / N0), a.y * (1.0f / N0),
                               a.z * (1.0f / N0), a.w * (1.0f / N0));
        ((float4*)sbuf)[tid] = m;
    }
    __syncthreads();

    // ======================= ROUND 1 (49 -> 36) =============================
    {   // h = gelu(s @ W1 + b1): up to 5 outputs per warp
        const float4* s4 = (const float4*)sbuf;
        #pragma unroll
        for (int jj = 0; jj < 5; jj++) {
            int j = warp + jj * WARPS;
            if (j < MID) {
                float acc = w1_dot(g_w1t[0] + j * CH, s4, lane);
                #pragma unroll
                for (int o = 16; o; o >>= 1) acc += __shfl_xor_sync(0xffffffffu, acc, o);
                if (lane == 0) {
                    float z = acc + b1a[j];
                    hbuf[j] = 0.5f * z * (1.0f + erff(z * 0.70710678118654752f));
                }
            }
        }
    }
    __syncthreads();

    // gates1: strided channels (packed W2, coalesced)
    {
        const uint2* W2p = (const uint2*)g_w2p[0];
        for (int c = tid; c < CH; c += THREADS) {
            float a = b2a[c] + w2_dot(W2p, hbuf, c);
            gat[c] = 1.0f / (1.0f + expf(-a));
        }
    }
    __syncthreads();

    // ts1[r] = sum_c (x*g)^2: warp per row, float4
    {
        const float4* g4p = (const float4*)gat;
        #pragma unroll
        for (int ii = 0; ii < 5; ii++) {
            int r = warp + ii * WARPS;
            if (r < N0) {
                const float4* row = (const float4*)(xb + (size_t)r * CH);
                float acc = 0.f;
                #pragma unroll
                for (int k = 0; k < 6; k++) {
                    float4 a = __ldcg(row + lane + 32 * k);
                    float4 g = g4p[lane + 32 * k];
                    float v;
                    v = a.x * g.x; acc += v * v;
                    v = a.y * g.y; acc += v * v;
                    v = a.z * g.z; acc += v * v;
                    v = a.w * g.w; acc += v * v;
                }
                #pragma unroll
                for (int o = 16; o; o >>= 1) acc += __shfl_xor_sync(0xffffffffu, acc, o);
                if (lane == 0) ts[r] = acc;
            }
        }
    }
    __syncthreads();

    // rank-select top-36 (== jax top_k order); 13 unselected to uns
    if (tid < N0) {
        float mine = ts[tid];
        int rank = 0;
        #pragma unroll
        for (int j = 0; j < N0; j++) {
            float tj = ts[j];
            rank += (tj > mine) || (tj == mine && j < tid);
        }
        if (rank < K1) list[rank] = tid;
        else           uns[rank - K1] = tid;
    }
    __syncthreads();

    // ======================= ROUND 2 (36 -> 24) =============================
    // csum36 = csum49 - 13 unselected rows; s2 = gat*csum36/36  (float4)
    if (tid < 192) {
        float4 c = ((float4*)csum)[tid];
        #pragma unroll
        for (int i = 0; i < N0 - K1; i++) {
            float4 v = __ldcg((const float4*)(xb + (size_t)uns[i] * CH) + tid);
            c.x -= v.x; c.y -= v.y; c.z -= v.z; c.w -= v.w;
        }
        ((float4*)csum)[tid] = c;
        float4 g = ((float4*)gat)[tid];
        float4 s = make_float4(c.x * g.x * (1.0f / K1), c.y * g.y * (1.0f / K1),
                               c.z * g.z * (1.0f / K1), c.w * g.w * (1.0f / K1));
        ((float4*)sbuf)[tid] = s;
    }
    __syncthreads();

    {
        const float4* s4 = (const float4*)sbuf;
        #pragma unroll
        for (int jj = 0; jj < 5; jj++) {
            int j = warp + jj * WARPS;
            if (j < MID) {
                float acc = w1_dot(g_w1t[1] + j * CH, s4, lane);
                #pragma unroll
                for (int o = 16; o; o >>= 1) acc += __shfl_xor_sync(0xffffffffu, acc, o);
                if (lane == 0) {
                    float z = acc + b1b[j];
                    hbuf[j] = 0.5f * z * (1.0f + erff(z * 0.70710678118654752f));
                }
            }
        }
    }
    __syncthreads();

    // gat *= gates2
    {
        const uint2* W2p = (const uint2*)g_w2p[1];
        for (int c = tid; c < CH; c += THREADS) {
            float a = b2b[c] + w2_dot(W2p, hbuf, c);
            gat[c] *= 1.0f / (1.0f + expf(-a));
        }
    }
    __syncthreads();

    // ts2 over 36 selected rows (cumulative gate)
    {
        const float4* g4p = (const float4*)gat;
        #pragma unroll
        for (int ii = 0; ii < 4; ii++) {
            int i = warp + ii * WARPS;
            if (i < K1) {
                const float4* row = (const float4*)(xb + (size_t)list[i] * CH);
                float acc = 0.f;
                #pragma unroll
                for (int k = 0; k < 6; k++) {
                    float4 a = __ldcg(row + lane + 32 * k);
                    float4 g = g4p[lane + 32 * k];
                    float v;
                    v = a.x * g.x; acc += v * v;
                    v = a.y * g.y; acc += v * v;
                    v = a.z * g.z; acc += v * v;
                    v = a.w * g.w; acc += v * v;
                }
                #pragma unroll
                for (int o = 16; o; o >>= 1) acc += __shfl_xor_sync(0xffffffffu, acc, o);
                if (lane == 0) ts[i] = acc;
            }
        }
    }
    __syncthreads();

    // top-24 of 36: record the 12 removed rows
    if (tid < K1) {
        float mine = ts[tid];
        int rank = 0;
        int row = list[tid];
        #pragma unroll
        for (int j = 0; j < K1; j++) {
            float tj = ts[j];
            rank += (tj > mine) || (tj == mine && j < tid);
        }
        if (rank >= K2) uns2[rank - K2] = row;
    }
    __syncthreads();

    // pooled = gat * (csum36 - 12 removed rows) / 24  (float4)
    if (tid < 192) {
        float4 c = ((float4*)csum)[tid];
        #pragma unroll
        for (int i = 0; i < K1 - K2; i++) {
            float4 v = __ldcg((const float4*)(xb + (size_t)uns2[i] * CH) + tid);
            c.x -= v.x; c.y -= v.y; c.z -= v.z; c.w -= v.w;
        }
        float4 g = ((float4*)gat)[tid];
        float4 s = make_float4(c.x * g.x * (1.0f / K2), c.y * g.y * (1.0f / K2),
                               c.z * g.z * (1.0f / K2), c.w * g.w * (1.0f / K2));
        ((float4*)sbuf)[tid] = s;
    }
    __syncthreads();

    // ---- LayerNorm stats (float4, threads 0..191 = warps 0..5) ----
    {
        float p1 = 0.f, p2 = 0.f;
        float4 v4;
        if (tid < 192) {
            v4 = ((float4*)sbuf)[tid];
            p1 = v4.x + v4.y + v4.z + v4.w;
            p2 = v4.x*v4.x + v4.y*v4.y + v4.z*v4.z + v4.w*v4.w;
        }
        #pragma unroll
        for (int o = 16; o; o >>= 1) {
            p1 += __shfl_xor_sync(0xffffffffu, p1, o);
            p2 += __shfl_xor_sync(0xffffffffu, p2, o);
        }
        if (lane == 0 && warp < 6) { red[warp] = p1; red[8 + warp] = p2; }
        __syncthreads();
        if (tid == 0) {
            float m = 0.f, m2 = 0.f;
            #pragma unroll
            for (int w = 0; w < 6; w++) { m += red[w]; m2 += red[8 + w]; }
            m  *= (1.0f / CH);
            m2 *= (1.0f / CH);
            red[16] = m;
            red[17] = rsqrtf(m2 - m * m + 1e-5f);
        }
        __syncthreads();
        if (tid < 192) {
            float mu = red[16], inv = red[17];
            float4 lg = __ldg((const float4*)ln_g + tid);
            float4 lb = __ldg((const float4*)ln_b + tid);
            float4 nv;
            nv.x = (v4.x - mu) * inv * lg.x + lb.x;
            nv.y = (v4.y - mu) * inv * lg.y + lb.y;
            nv.z = (v4.z - mu) * inv * lg.z + lb.z;
            nv.w = (v4.w - mu) * inv * lg.w + lb.w;
            ((float4*)gat)[tid] = nv;
        }
    }
    __syncthreads();

    // ---- classifier: 5 outputs, one warp each ----
    if (warp < 5) {
        const float* wr = g_clswt + warp * CH;
        float acc = 0.f;
        #pragma unroll
        for (int k = 0; k < CH / 32; k++)
            acc += gat[lane + 32 * k] * wr[lane + 32 * k];
        #pragma unroll
        for (int o = 16; o; o >>= 1) acc += __shfl_xor_sync(0xffffffffu, acc, o);
        if (lane == 0) out[b * 5 + warp] = acc + cls_b[warp];
    }
}

extern "C" void kernel_launch(void* const* d_in, const int* in_sizes, int n_in,
                              void* d_out, int out_size) {
    const float* x    = (const float*)d_in[0];
    const float* w1a  = (const float*)d_in[1];
    const float* b1a  = (const float*)d_in[2];
    const float* w2a  = (const float*)d_in[3];
    const float* b2a  = (const float*)d_in[4];
    const float* w1b  = (const float*)d_in[5];
    const float* b1b  = (const float*)d_in[6];
    const float* w2b  = (const float*)d_in[7];
    const float* b2b  = (const float*)d_in[8];
    const float* lng  = (const float*)d_in[9];
    const float* lnb  = (const float*)d_in[10];
    const float* clsw = (const float*)d_in[11];
    const float* clsb = (const float*)d_in[12];
    float* out = (float*)d_out;

    cudaFuncSetAttribute(coatgft_kernel,
                         cudaFuncAttributeMaxDynamicSharedMemorySize, SM_BYTES);

    convert_weights_kernel<<<(MID * CH + 255) / 256, 256>>>(w1a, w2a, w1b, w2b, clsw);
    coatgft_kernel<<<BATCH, THREADS, SM_BYTES>>>(x, b1a, b2a, b1b, b2b,
                                                 lng, lnb, clsb, out);
}